// round 2
// baseline (speedup 1.0000x reference)
#include <cuda_runtime.h>
#include <mma.h>
#include <cstdint>

using namespace nvcuda;

// ---------------- problem constants ----------------
#define N_NODES 8192
#define IN_DIM  64
#define OUT_DIM 64
#define SUPPORT 4

// ---------------- GEMM tiling ----------------
#define BM 64
#define BK 32
#define STAGES 5
#define APITCH 36                          // padded row pitch (floats): 144B, 16B-aligned, bank-shifted
#define STAGE_FLOATS (2 * 64 * APITCH)     // A tile (64 rows) + B tile (64 rows)
#define K_ITERS (SUPPORT * (N_NODES / BK)) // 1024
#define GEMM_SMEM (STAGES * STAGE_FLOATS * 4)
#define OPITCH 72                          // epilogue smem pitch

// ---------------- device scratch (no allocs allowed) ----------------
// YT[s][n][k] = Y_s[k][n], tf32-pre-rounded fp32. 8 MB -> L2 resident.
__device__ __align__(1024) float g_YT[SUPPORT * OUT_DIM * N_NODES];

// ---------------- cp.async helpers (compute_103-legal, sm_80+) ----------------
__device__ __forceinline__ uint32_t smem_u32(const void* p) {
    uint32_t a;
    asm("{ .reg .u64 t; cvta.to.shared.u64 t, %1; cvt.u32.u64 %0, t; }" : "=r"(a) : "l"(p));
    return a;
}
#define CP_ASYNC16(dst_u32, src_ptr) \
    asm volatile("cp.async.cg.shared.global [%0], [%1], 16;" :: "r"(dst_u32), "l"(src_ptr) : "memory")
#define CP_COMMIT() asm volatile("cp.async.commit_group;" ::: "memory")
#define CP_WAIT(n)  asm volatile("cp.async.wait_group %0;" :: "n"(n) : "memory")

// ---------------- kernel 1: Y^T[s][n][k] = sum_i X[k,i] * V_s[i,n] ----------------
__global__ void y_kernel(const float* __restrict__ X,
                         const float* __restrict__ Kmat,
                         const float* __restrict__ comp,
                         float* __restrict__ YT)
{
    __shared__ float Vs[IN_DIM][OUT_DIM + 1];
    __shared__ float Xs[64][IN_DIM + 1];
    const int s  = blockIdx.y;
    const int j0 = blockIdx.x * 64;
    const float c0 = comp[s * 2 + 0];
    const float c1 = comp[s * 2 + 1];

    for (int idx = threadIdx.x; idx < IN_DIM * OUT_DIM; idx += blockDim.x) {
        int i = idx >> 6, o = idx & 63;
        Vs[i][o] = c0 * Kmat[i * OUT_DIM + o] + c1 * Kmat[(IN_DIM + i) * OUT_DIM + o];
    }
    for (int idx = threadIdx.x; idx < 64 * IN_DIM; idx += blockDim.x) {
        int j = idx >> 6, i = idx & 63;
        Xs[j][i] = X[(size_t)(j0 + j) * IN_DIM + i];
    }
    __syncthreads();

    const int jq = (threadIdx.x & 15) * 4;
    const int oq = (threadIdx.x >> 4) * 4;
    float acc[4][4] = {};
    #pragma unroll 8
    for (int i = 0; i < IN_DIM; i++) {
        float xv[4], vv[4];
        #pragma unroll
        for (int a = 0; a < 4; a++) xv[a] = Xs[jq + a][i];
        #pragma unroll
        for (int b = 0; b < 4; b++) vv[b] = Vs[i][oq + b];
        #pragma unroll
        for (int a = 0; a < 4; a++)
            #pragma unroll
            for (int b = 0; b < 4; b++)
                acc[a][b] = fmaf(xv[a], vv[b], acc[a][b]);
    }

    uint32_t* yt_u = reinterpret_cast<uint32_t*>(YT);
    #pragma unroll
    for (int b = 0; b < 4; b++) {
        #pragma unroll
        for (int a = 0; a < 4; a++) {
            uint32_t t;
            asm("cvt.rna.tf32.f32 %0, %1;" : "=r"(t) : "f"(acc[a][b]));   // pre-round to tf32
            yt_u[((size_t)s * OUT_DIM + oq + b) * N_NODES + j0 + jq + a] = t;
        }
    }
}

// ---------------- kernel 2: wmma tf32 GEMM ----------------
// out[m,n] = relu( sum_{s,k} A[s,m,k] * YT[s][n][k] + bias[n] )
__global__ void __launch_bounds__(128, 1)
rgcn_gemm_kernel(const float* __restrict__ A,
                 const float* __restrict__ YT,
                 const float* __restrict__ bias,
                 float* __restrict__ out)
{
    extern __shared__ float sm[];
    const uint32_t sm_base = smem_u32(sm);

    const int tid = threadIdx.x;
    const int wid = tid >> 5;
    const int m0  = blockIdx.x * BM;

    // warp tiling: 2x2 over the 64x64 CTA tile (each warp: 32 rows x 32 cols)
    const int mbase = (wid & 1) * 32;
    const int nbase = (wid >> 1) * 32;

    wmma::fragment<wmma::accumulator, 16, 16, 8, float> acc[2][2];
    #pragma unroll
    for (int i = 0; i < 2; i++)
        #pragma unroll
        for (int j = 0; j < 2; j++)
            wmma::fill_fragment(acc[i][j], 0.0f);

    // ---- stage loader: 64x32 A rows + 64x32 B rows, padded pitch ----
    auto issue = [&](int it) {
        const int st = it % STAGES;
        const int s  = it >> 8;                 // it / 256
        const int k0 = (it & 255) << 5;         // *32
        const uint32_t a_s = sm_base + (uint32_t)(st * STAGE_FLOATS) * 4u;
        const uint32_t b_s = a_s + 64u * APITCH * 4u;
        const float* Ab = A  + ((size_t)s * N_NODES + m0) * N_NODES + k0;
        const float* Bb = YT + ((size_t)s * OUT_DIM) * N_NODES + k0;
        #pragma unroll
        for (int i = 0; i < 4; i++) {
            int v   = tid + i * 128;            // 512 float4 per matrix
            int row = v >> 3;
            int c   = (v & 7) * 4;
            CP_ASYNC16(a_s + (uint32_t)(row * APITCH + c) * 4u, Ab + (size_t)row * N_NODES + c);
            CP_ASYNC16(b_s + (uint32_t)(row * APITCH + c) * 4u, Bb + (size_t)row * N_NODES + c);
        }
    };

    // prologue: fill STAGES-1 stages
    #pragma unroll
    for (int p = 0; p < STAGES - 1; p++) { issue(p); CP_COMMIT(); }

    for (int it = 0; it < K_ITERS; ++it) {
        CP_WAIT(STAGES - 2);
        __syncthreads();

        // refill the stage computed last iteration (all warps are past the sync)
        const int nx = it + STAGES - 1;
        if (nx < K_ITERS) issue(nx);
        CP_COMMIT();

        const float* at = sm + (it % STAGES) * STAGE_FLOATS;
        const float* bt = at + 64 * APITCH;

        #pragma unroll
        for (int kk = 0; kk < 4; kk++) {        // 4 k8-steps per BK=32
            wmma::fragment<wmma::matrix_a, 16, 16, 8, wmma::precision::tf32, wmma::row_major> af[2];
            wmma::fragment<wmma::matrix_b, 16, 16, 8, wmma::precision::tf32, wmma::col_major> bf[2];
            #pragma unroll
            for (int i = 0; i < 2; i++) {
                wmma::load_matrix_sync(af[i], at + (mbase + 16 * i) * APITCH + kk * 8, APITCH);
                #pragma unroll
                for (int e = 0; e < af[i].num_elements; e++)
                    af[i].x[e] = wmma::__float_to_tf32(af[i].x[e]);   // rna round A
            }
            #pragma unroll
            for (int j = 0; j < 2; j++) {
                // B smem layout [n][k] pitch APITCH == col-major (k fast) with ld=APITCH
                wmma::load_matrix_sync(bf[j], bt + (nbase + 16 * j) * APITCH + kk * 8, APITCH);
                // YT is pre-rounded to tf32 -> no conversion needed
            }
            #pragma unroll
            for (int i = 0; i < 2; i++)
                #pragma unroll
                for (int j = 0; j < 2; j++)
                    wmma::mma_sync(acc[i][j], af[i], bf[j], acc[i][j]);
        }
    }

    // ---- epilogue: fused bias + relu via smem (reuse stage 0) ----
    __syncthreads();
    #pragma unroll
    for (int i = 0; i < 2; i++)
        #pragma unroll
        for (int j = 0; j < 2; j++)
            wmma::store_matrix_sync(sm + (mbase + 16 * i) * OPITCH + (nbase + 16 * j),
                                    acc[i][j], OPITCH, wmma::mem_row_major);
    __syncthreads();

    #pragma unroll
    for (int i = 0; i < 8; i++) {
        int v   = tid + i * 128;                // 1024 float4 outputs
        int row = v >> 4;
        int c   = (v & 15) * 4;
        float4 r;
        r.x = fmaxf(sm[row * OPITCH + c + 0] + __ldg(bias + c + 0), 0.0f);
        r.y = fmaxf(sm[row * OPITCH + c + 1] + __ldg(bias + c + 1), 0.0f);
        r.z = fmaxf(sm[row * OPITCH + c + 2] + __ldg(bias + c + 2), 0.0f);
        r.w = fmaxf(sm[row * OPITCH + c + 3] + __ldg(bias + c + 3), 0.0f);
        *reinterpret_cast<float4*>(out + (size_t)(m0 + row) * OUT_DIM + c) = r;
    }
}

// ---------------- host launcher ----------------
extern "C" void kernel_launch(void* const* d_in, const int* in_sizes, int n_in,
                              void* d_out, int out_size)
{
    const float* features = (const float*)d_in[0];
    const float* A        = (const float*)d_in[1];
    const float* kern     = (const float*)d_in[2];
    const float* comp     = (const float*)d_in[3];
    const float* bias     = (const float*)d_in[4];
    float* out = (float*)d_out;

    float* yt = nullptr;
    cudaGetSymbolAddress((void**)&yt, g_YT);

    // 1) Y^T = (X @ V_s)^T, tf32-pre-rounded
    y_kernel<<<dim3(N_NODES / 64, SUPPORT), 256>>>(features, kern, comp, yt);

    // 2) main GEMM + fused bias/relu
    cudaFuncSetAttribute(rgcn_gemm_kernel,
                         cudaFuncAttributeMaxDynamicSharedMemorySize, GEMM_SMEM);
    rgcn_gemm_kernel<<<N_NODES / BM, 128, GEMM_SMEM>>>(A, yt, bias, out);
}

// round 3
// speedup vs baseline: 1.2106x; 1.2106x over previous
#include <cuda_runtime.h>
#include <mma.h>
#include <cstdint>

using namespace nvcuda;

// ---------------- problem constants ----------------
#define N_NODES 8192
#define IN_DIM  64
#define OUT_DIM 64
#define SUPPORT 4

// ---------------- GEMM tiling ----------------
#define BM 128
#define BK 32
#define STAGES 6
#define APITCH 36                              // padded pitch (floats): 144B, 16B aligned
#define A_STAGE_FLOATS (BM * APITCH)           // 128 rows
#define B_STAGE_FLOATS (OUT_DIM * APITCH)      // 64 rows
#define STAGE_FLOATS (A_STAGE_FLOATS + B_STAGE_FLOATS)
#define SPLITK 2
#define S_PER_CTA (SUPPORT / SPLITK)           // 2 relations per CTA
#define K_ITERS (S_PER_CTA * (N_NODES / BK))   // 512
#define GEMM_SMEM (STAGES * STAGE_FLOATS * 4)  // 165,888 B

// ---------------- device scratch (no allocs allowed) ----------------
__device__ __align__(1024) float g_YT[SUPPORT * OUT_DIM * N_NODES];     // 8 MB
__device__ __align__(1024) float g_part[SPLITK * N_NODES * OUT_DIM];    // 4 MB

// ---------------- helpers ----------------
__device__ __forceinline__ uint32_t smem_u32(const void* p) {
    uint32_t a;
    asm("{ .reg .u64 t; cvta.to.shared.u64 t, %1; cvt.u32.u64 %0, t; }" : "=r"(a) : "l"(p));
    return a;
}
#define CP_ASYNC16(dst_u32, src_ptr) \
    asm volatile("cp.async.cg.shared.global [%0], [%1], 16;" :: "r"(dst_u32), "l"(src_ptr) : "memory")
#define CP_COMMIT() asm volatile("cp.async.commit_group;" ::: "memory")
#define CP_WAIT(n)  asm volatile("cp.async.wait_group %0;" :: "n"(n) : "memory")

// ---------------- kernel 1: Y^T[s][n][k] = sum_i X[k,i] * V_s[i,n] ----------------
__global__ void y_kernel(const float* __restrict__ X,
                         const float* __restrict__ Kmat,
                         const float* __restrict__ comp,
                         float* __restrict__ YT)
{
    __shared__ float Vs[IN_DIM][OUT_DIM + 1];
    __shared__ float Xs[64][IN_DIM + 1];
    const int s  = blockIdx.y;
    const int j0 = blockIdx.x * 64;
    const float c0 = comp[s * 2 + 0];
    const float c1 = comp[s * 2 + 1];

    for (int idx = threadIdx.x; idx < IN_DIM * OUT_DIM; idx += blockDim.x) {
        int i = idx >> 6, o = idx & 63;
        Vs[i][o] = c0 * Kmat[i * OUT_DIM + o] + c1 * Kmat[(IN_DIM + i) * OUT_DIM + o];
    }
    for (int idx = threadIdx.x; idx < 64 * IN_DIM; idx += blockDim.x) {
        int j = idx >> 6, i = idx & 63;
        Xs[j][i] = X[(size_t)(j0 + j) * IN_DIM + i];
    }
    __syncthreads();

    const int jq = (threadIdx.x & 15) * 4;
    const int oq = (threadIdx.x >> 4) * 4;
    float acc[4][4] = {};
    #pragma unroll 8
    for (int i = 0; i < IN_DIM; i++) {
        float xv[4], vv[4];
        #pragma unroll
        for (int a = 0; a < 4; a++) xv[a] = Xs[jq + a][i];
        #pragma unroll
        for (int b = 0; b < 4; b++) vv[b] = Vs[i][oq + b];
        #pragma unroll
        for (int a = 0; a < 4; a++)
            #pragma unroll
            for (int b = 0; b < 4; b++)
                acc[a][b] = fmaf(xv[a], vv[b], acc[a][b]);
    }

    uint32_t* yt_u = reinterpret_cast<uint32_t*>(YT);
    #pragma unroll
    for (int b = 0; b < 4; b++) {
        #pragma unroll
        for (int a = 0; a < 4; a++) {
            uint32_t t;
            asm("cvt.rna.tf32.f32 %0, %1;" : "=r"(t) : "f"(acc[a][b]));   // pre-round to tf32
            yt_u[((size_t)s * OUT_DIM + oq + b) * N_NODES + j0 + jq + a] = t;
        }
    }
}

// ---------------- kernel 2: wmma tf32 GEMM, split-K ----------------
// part[kv][m,n] = sum over relations {2kv, 2kv+1} of A[s,m,:] . YT[s][n][:]
__global__ void __launch_bounds__(256, 1)
rgcn_gemm_kernel(const float* __restrict__ A,
                 const float* __restrict__ YT,
                 float* __restrict__ part)
{
    extern __shared__ float sm[];
    const uint32_t sm_base = smem_u32(sm);

    const int tid = threadIdx.x;
    const int wid = tid >> 5;
    const int m0  = blockIdx.x * BM;
    const int kv  = blockIdx.y;                 // split-K index (0/1)
    const int s0  = kv * S_PER_CTA;

    // warp grid: 4 (M) x 2 (N); each warp 32x32
    const int mbase = (wid & 3) * 32;
    const int nbase = (wid >> 2) * 32;

    wmma::fragment<wmma::accumulator, 16, 16, 8, float> acc[2][2];
    #pragma unroll
    for (int i = 0; i < 2; i++)
        #pragma unroll
        for (int j = 0; j < 2; j++)
            wmma::fill_fragment(acc[i][j], 0.0f);

    // ---- stage loader: 128x32 A + 64x32 B (padded pitch), 256 threads ----
    auto issue = [&](int it) {
        const int st = it % STAGES;
        const int s  = s0 + (it >> 8);          // it / 256
        const int k0 = (it & 255) << 5;         // * 32
        const uint32_t a_s = sm_base + (uint32_t)(st * STAGE_FLOATS) * 4u;
        const uint32_t b_s = a_s + (uint32_t)A_STAGE_FLOATS * 4u;
        const float* Ab = A  + ((size_t)s * N_NODES + m0) * N_NODES + k0;
        const float* Bb = YT + ((size_t)s * OUT_DIM) * N_NODES + k0;
        #pragma unroll
        for (int i = 0; i < 4; i++) {           // 1024 float4 of A
            int v   = tid + i * 256;
            int row = v >> 3;
            int c   = (v & 7) * 4;
            CP_ASYNC16(a_s + (uint32_t)(row * APITCH + c) * 4u, Ab + (size_t)row * N_NODES + c);
        }
        #pragma unroll
        for (int i = 0; i < 2; i++) {           // 512 float4 of B
            int v   = tid + i * 256;
            int row = v >> 3;
            int c   = (v & 7) * 4;
            CP_ASYNC16(b_s + (uint32_t)(row * APITCH + c) * 4u, Bb + (size_t)row * N_NODES + c);
        }
    };

    #pragma unroll
    for (int p = 0; p < STAGES - 1; p++) { issue(p); CP_COMMIT(); }

    for (int it = 0; it < K_ITERS; ++it) {
        CP_WAIT(STAGES - 2);
        __syncthreads();

        const int nx = it + STAGES - 1;
        if (nx < K_ITERS) issue(nx);
        CP_COMMIT();

        const float* at = sm + (it % STAGES) * STAGE_FLOATS;
        const float* bt = at + A_STAGE_FLOATS;

        #pragma unroll
        for (int kk = 0; kk < 4; kk++) {        // 4 k8-steps per BK=32
            wmma::fragment<wmma::matrix_a, 16, 16, 8, wmma::precision::tf32, wmma::row_major> af[2];
            wmma::fragment<wmma::matrix_b, 16, 16, 8, wmma::precision::tf32, wmma::col_major> bf[2];
            #pragma unroll
            for (int i = 0; i < 2; i++) {
                wmma::load_matrix_sync(af[i], at + (mbase + 16 * i) * APITCH + kk * 8, APITCH);
                #pragma unroll
                for (int e = 0; e < af[i].num_elements; e++)
                    af[i].x[e] = wmma::__float_to_tf32(af[i].x[e]);   // rna round A
            }
            #pragma unroll
            for (int j = 0; j < 2; j++)
                wmma::load_matrix_sync(bf[j], bt + (nbase + 16 * j) * APITCH + kk * 8, APITCH);
            #pragma unroll
            for (int i = 0; i < 2; i++)
                #pragma unroll
                for (int j = 0; j < 2; j++)
                    wmma::mma_sync(acc[i][j], af[i], bf[j], acc[i][j]);
        }
    }

    // ---- write partial tile directly to global (16-float contiguous rows) ----
    float* pbase = part + (size_t)kv * N_NODES * OUT_DIM + (size_t)(m0) * OUT_DIM;
    #pragma unroll
    for (int i = 0; i < 2; i++)
        #pragma unroll
        for (int j = 0; j < 2; j++)
            wmma::store_matrix_sync(pbase + (size_t)(mbase + 16 * i) * OUT_DIM + nbase + 16 * j,
                                    acc[i][j], OUT_DIM, wmma::mem_row_major);
}

// ---------------- kernel 3: reduce + bias + relu ----------------
__global__ void reduce_kernel(const float* __restrict__ part,
                              const float* __restrict__ bias,
                              float* __restrict__ out)
{
    const int v = blockIdx.x * blockDim.x + threadIdx.x;   // float4 index
    const int idx = v * 4;
    const int c = idx & (OUT_DIM - 1);
    float4 p0 = *reinterpret_cast<const float4*>(part + idx);
    float4 p1 = *reinterpret_cast<const float4*>(part + (size_t)N_NODES * OUT_DIM + idx);
    float4 r;
    r.x = fmaxf(p0.x + p1.x + __ldg(bias + c + 0), 0.0f);
    r.y = fmaxf(p0.y + p1.y + __ldg(bias + c + 1), 0.0f);
    r.z = fmaxf(p0.z + p1.z + __ldg(bias + c + 2), 0.0f);
    r.w = fmaxf(p0.w + p1.w + __ldg(bias + c + 3), 0.0f);
    *reinterpret_cast<float4*>(out + idx) = r;
}

// ---------------- host launcher ----------------
extern "C" void kernel_launch(void* const* d_in, const int* in_sizes, int n_in,
                              void* d_out, int out_size)
{
    const float* features = (const float*)d_in[0];
    const float* A        = (const float*)d_in[1];
    const float* kern     = (const float*)d_in[2];
    const float* comp     = (const float*)d_in[3];
    const float* bias     = (const float*)d_in[4];
    float* out = (float*)d_out;

    float* yt = nullptr;
    float* part = nullptr;
    cudaGetSymbolAddress((void**)&yt, g_YT);
    cudaGetSymbolAddress((void**)&part, g_part);

    // 1) Y^T = (X @ V_s)^T, tf32-pre-rounded
    y_kernel<<<dim3(N_NODES / 64, SUPPORT), 256>>>(features, kern, comp, yt);

    // 2) split-K GEMM into partials
    cudaFuncSetAttribute(rgcn_gemm_kernel,
                         cudaFuncAttributeMaxDynamicSharedMemorySize, GEMM_SMEM);
    rgcn_gemm_kernel<<<dim3(N_NODES / BM, SPLITK), 256, GEMM_SMEM>>>(A, yt, part);

    // 3) reduce partials + bias + relu
    reduce_kernel<<<(N_NODES * OUT_DIM / 4) / 256, 256>>>(part, bias, out);
}

// round 4
// speedup vs baseline: 1.3581x; 1.1219x over previous
#include <cuda_runtime.h>
#include <mma.h>
#include <cstdint>

using namespace nvcuda;

// ---------------- problem constants ----------------
#define N_NODES 8192
#define IN_DIM  64
#define OUT_DIM 64
#define SUPPORT 4

// ---------------- GEMM tiling ----------------
#define BM 128
#define BK 32
#define STAGES 4
#define APITCH 36                              // padded pitch (floats): 144B, 16B aligned
#define A_STAGE_FLOATS (BM * APITCH)
#define B_STAGE_FLOATS (OUT_DIM * APITCH)
#define STAGE_FLOATS (A_STAGE_FLOATS + B_STAGE_FLOATS)
#define SPLITK 4                               // one relation per CTA
#define K_ITERS (N_NODES / BK)                 // 256
#define GEMM_SMEM (STAGES * STAGE_FLOATS * 4)  // 110,592 B -> 2 CTAs/SM

// ---------------- device scratch (no allocs allowed) ----------------
__device__ __align__(1024) float g_YT[SUPPORT * OUT_DIM * N_NODES];     // 8 MB
__device__ __align__(1024) float g_part[SPLITK * N_NODES * OUT_DIM];    // 8 MB

// ---------------- helpers ----------------
__device__ __forceinline__ uint32_t smem_u32(const void* p) {
    uint32_t a;
    asm("{ .reg .u64 t; cvta.to.shared.u64 t, %1; cvt.u32.u64 %0, t; }" : "=r"(a) : "l"(p));
    return a;
}
#define CP_ASYNC16(dst_u32, src_ptr) \
    asm volatile("cp.async.cg.shared.global [%0], [%1], 16;" :: "r"(dst_u32), "l"(src_ptr) : "memory")
#define CP_COMMIT() asm volatile("cp.async.commit_group;" ::: "memory")
#define CP_WAIT(n)  asm volatile("cp.async.wait_group %0;" :: "n"(n) : "memory")

// ---------------- kernel 1: Y^T[s][n][k] = sum_i X[k,i] * V_s[i,n] ----------------
__global__ void y_kernel(const float* __restrict__ X,
                         const float* __restrict__ Kmat,
                         const float* __restrict__ comp,
                         float* __restrict__ YT)
{
    __shared__ float Vs[IN_DIM][OUT_DIM + 1];
    __shared__ float Xs[64][IN_DIM + 1];
    const int s  = blockIdx.y;
    const int j0 = blockIdx.x * 64;
    const float c0 = comp[s * 2 + 0];
    const float c1 = comp[s * 2 + 1];

    for (int idx = threadIdx.x; idx < IN_DIM * OUT_DIM; idx += blockDim.x) {
        int i = idx >> 6, o = idx & 63;
        Vs[i][o] = c0 * Kmat[i * OUT_DIM + o] + c1 * Kmat[(IN_DIM + i) * OUT_DIM + o];
    }
    for (int idx = threadIdx.x; idx < 64 * IN_DIM; idx += blockDim.x) {
        int j = idx >> 6, i = idx & 63;
        Xs[j][i] = X[(size_t)(j0 + j) * IN_DIM + i];
    }
    __syncthreads();

    const int jq = (threadIdx.x & 15) * 4;
    const int oq = (threadIdx.x >> 4) * 4;
    float acc[4][4] = {};
    #pragma unroll 8
    for (int i = 0; i < IN_DIM; i++) {
        float xv[4], vv[4];
        #pragma unroll
        for (int a = 0; a < 4; a++) xv[a] = Xs[jq + a][i];
        #pragma unroll
        for (int b = 0; b < 4; b++) vv[b] = Vs[i][oq + b];
        #pragma unroll
        for (int a = 0; a < 4; a++)
            #pragma unroll
            for (int b = 0; b < 4; b++)
                acc[a][b] = fmaf(xv[a], vv[b], acc[a][b]);
    }

    uint32_t* yt_u = reinterpret_cast<uint32_t*>(YT);
    #pragma unroll
    for (int b = 0; b < 4; b++) {
        #pragma unroll
        for (int a = 0; a < 4; a++) {
            uint32_t t;
            asm("cvt.rna.tf32.f32 %0, %1;" : "=r"(t) : "f"(acc[a][b]));   // pre-round to tf32
            yt_u[((size_t)s * OUT_DIM + oq + b) * N_NODES + j0 + jq + a] = t;
        }
    }
}

// ---------------- kernel 2: wmma tf32 GEMM, split-K (1 relation / CTA) ----------------
__global__ void __launch_bounds__(256, 2)
rgcn_gemm_kernel(const float* __restrict__ A,
                 const float* __restrict__ YT,
                 float* __restrict__ part)
{
    extern __shared__ float sm[];
    const uint32_t sm_base = smem_u32(sm);

    const int tid = threadIdx.x;
    const int wid = tid >> 5;
    const int m0  = blockIdx.x * BM;
    const int s   = blockIdx.y;                 // relation == split-K index

    // warp grid: 4 (M) x 2 (N); each warp 32x32
    const int mbase = (wid & 3) * 32;
    const int nbase = (wid >> 2) * 32;

    wmma::fragment<wmma::accumulator, 16, 16, 8, float> acc[2][2];
    #pragma unroll
    for (int i = 0; i < 2; i++)
        #pragma unroll
        for (int j = 0; j < 2; j++)
            wmma::fill_fragment(acc[i][j], 0.0f);

    const float* Abase = A  + ((size_t)s * N_NODES + m0) * N_NODES;
    const float* Bbase = YT + ((size_t)s * OUT_DIM) * N_NODES;

    auto issue = [&](int it) {
        const int st = it & (STAGES - 1);
        const int k0 = it << 5;                 // * 32
        const uint32_t a_s = sm_base + (uint32_t)(st * STAGE_FLOATS) * 4u;
        const uint32_t b_s = a_s + (uint32_t)A_STAGE_FLOATS * 4u;
        const float* Ab = Abase + k0;
        const float* Bb = Bbase + k0;
        #pragma unroll
        for (int i = 0; i < 4; i++) {           // 1024 float4 of A
            int v   = tid + i * 256;
            int row = v >> 3;
            int c   = (v & 7) * 4;
            CP_ASYNC16(a_s + (uint32_t)(row * APITCH + c) * 4u, Ab + (size_t)row * N_NODES + c);
        }
        #pragma unroll
        for (int i = 0; i < 2; i++) {           // 512 float4 of B
            int v   = tid + i * 256;
            int row = v >> 3;
            int c   = (v & 7) * 4;
            CP_ASYNC16(b_s + (uint32_t)(row * APITCH + c) * 4u, Bb + (size_t)row * N_NODES + c);
        }
    };

    #pragma unroll
    for (int p = 0; p < STAGES - 1; p++) { issue(p); CP_COMMIT(); }

    for (int it = 0; it < K_ITERS; ++it) {
        CP_WAIT(STAGES - 2);
        __syncthreads();

        const int nx = it + STAGES - 1;
        if (nx < K_ITERS) issue(nx);
        CP_COMMIT();

        const float* at = sm + (it & (STAGES - 1)) * STAGE_FLOATS;
        const float* bt = at + A_STAGE_FLOATS;

        #pragma unroll
        for (int kk = 0; kk < 4; kk++) {        // 4 k8-steps per BK=32
            wmma::fragment<wmma::matrix_a, 16, 16, 8, wmma::precision::tf32, wmma::row_major> af[2];
            wmma::fragment<wmma::matrix_b, 16, 16, 8, wmma::precision::tf32, wmma::col_major> bf[2];
            #pragma unroll
            for (int i = 0; i < 2; i++) {
                wmma::load_matrix_sync(af[i], at + (mbase + 16 * i) * APITCH + kk * 8, APITCH);
                #pragma unroll
                for (int e = 0; e < af[i].num_elements; e++)
                    af[i].x[e] = wmma::__float_to_tf32(af[i].x[e]);   // rna round A
            }
            #pragma unroll
            for (int j = 0; j < 2; j++)
                wmma::load_matrix_sync(bf[j], bt + (nbase + 16 * j) * APITCH + kk * 8, APITCH);
            #pragma unroll
            for (int i = 0; i < 2; i++)
                #pragma unroll
                for (int j = 0; j < 2; j++)
                    wmma::mma_sync(acc[i][j], af[i], bf[j], acc[i][j]);
        }
    }

    // ---- write partial tile to global ----
    float* pbase = part + (size_t)s * N_NODES * OUT_DIM + (size_t)m0 * OUT_DIM;
    #pragma unroll
    for (int i = 0; i < 2; i++)
        #pragma unroll
        for (int j = 0; j < 2; j++)
            wmma::store_matrix_sync(pbase + (size_t)(mbase + 16 * i) * OUT_DIM + nbase + 16 * j,
                                    acc[i][j], OUT_DIM, wmma::mem_row_major);
}

// ---------------- kernel 3: reduce + bias + relu ----------------
__global__ void reduce_kernel(const float* __restrict__ part,
                              const float* __restrict__ bias,
                              float* __restrict__ out)
{
    const int v = blockIdx.x * blockDim.x + threadIdx.x;   // float4 index
    const int idx = v * 4;
    const int c = idx & (OUT_DIM - 1);
    float4 r;
    float4 p0 = *reinterpret_cast<const float4*>(part + idx);
    float4 p1 = *reinterpret_cast<const float4*>(part + 1ull * N_NODES * OUT_DIM + idx);
    float4 p2 = *reinterpret_cast<const float4*>(part + 2ull * N_NODES * OUT_DIM + idx);
    float4 p3 = *reinterpret_cast<const float4*>(part + 3ull * N_NODES * OUT_DIM + idx);
    r.x = fmaxf((p0.x + p1.x) + (p2.x + p3.x) + __ldg(bias + c + 0), 0.0f);
    r.y = fmaxf((p0.y + p1.y) + (p2.y + p3.y) + __ldg(bias + c + 1), 0.0f);
    r.z = fmaxf((p0.z + p1.z) + (p2.z + p3.z) + __ldg(bias + c + 2), 0.0f);
    r.w = fmaxf((p0.w + p1.w) + (p2.w + p3.w) + __ldg(bias + c + 3), 0.0f);
    *reinterpret_cast<float4*>(out + idx) = r;
}

// ---------------- host launcher ----------------
extern "C" void kernel_launch(void* const* d_in, const int* in_sizes, int n_in,
                              void* d_out, int out_size)
{
    const float* features = (const float*)d_in[0];
    const float* A        = (const float*)d_in[1];
    const float* kern     = (const float*)d_in[2];
    const float* comp     = (const float*)d_in[3];
    const float* bias     = (const float*)d_in[4];
    float* out = (float*)d_out;

    float* yt = nullptr;
    float* part = nullptr;
    cudaGetSymbolAddress((void**)&yt, g_YT);
    cudaGetSymbolAddress((void**)&part, g_part);

    // 1) Y^T = (X @ V_s)^T, tf32-pre-rounded
    y_kernel<<<dim3(N_NODES / 64, SUPPORT), 256>>>(features, kern, comp, yt);

    // 2) split-K GEMM into partials (one relation per CTA, 2 CTAs/SM)
    cudaFuncSetAttribute(rgcn_gemm_kernel,
                         cudaFuncAttributeMaxDynamicSharedMemorySize, GEMM_SMEM);
    rgcn_gemm_kernel<<<dim3(N_NODES / BM, SPLITK), 256, GEMM_SMEM>>>(A, yt, part);

    // 3) reduce partials + bias + relu
    reduce_kernel<<<(N_NODES * OUT_DIM / 4) / 256, 256>>>(part, bias, out);
}

// round 5
// speedup vs baseline: 2.6851x; 1.9772x over previous
#include <cuda_runtime.h>
#include <cstdint>

// ---------------- problem constants ----------------
#define N_NODES 8192
#define IN_DIM  64
#define OUT_DIM 64
#define SUPPORT 4

// ---------------- GEMM tiling ----------------
#define BM 128
#define BK 32
#define STAGES 4
#define APITCH 36                              // padded pitch (floats): 144B
#define PITCHB (APITCH * 4)                    // 144 bytes
#define A_STAGE_FLOATS (BM * APITCH)
#define B_STAGE_FLOATS (OUT_DIM * APITCH)
#define STAGE_FLOATS (A_STAGE_FLOATS + B_STAGE_FLOATS)
#define STAGE_BYTES (STAGE_FLOATS * 4)
#define SPLITK 4                               // one relation per CTA
#define K_ITERS (N_NODES / BK)                 // 256
#define GEMM_SMEM (STAGES * STAGE_BYTES)       // 110,592 B -> 2 CTAs/SM

// ---------------- device scratch (no allocs allowed) ----------------
__device__ __align__(1024) float g_YT[SUPPORT * OUT_DIM * N_NODES];     // 8 MB
__device__ __align__(1024) float g_part[SPLITK * N_NODES * OUT_DIM];    // 8 MB

// ---------------- helpers ----------------
__device__ __forceinline__ uint32_t smem_u32(const void* p) {
    uint32_t a;
    asm("{ .reg .u64 t; cvta.to.shared.u64 t, %1; cvt.u32.u64 %0, t; }" : "=r"(a) : "l"(p));
    return a;
}
#define CP_ASYNC16(dst_u32, src_ptr) \
    asm volatile("cp.async.cg.shared.global [%0], [%1], 16;" :: "r"(dst_u32), "l"(src_ptr) : "memory")
#define CP_COMMIT() asm volatile("cp.async.commit_group;" ::: "memory")
#define CP_WAIT(n)  asm volatile("cp.async.wait_group %0;" :: "n"(n) : "memory")

#define LDSM_X4(r0, r1, r2, r3, addr) \
    asm volatile("ldmatrix.sync.aligned.m8n8.x4.shared.b16 {%0,%1,%2,%3}, [%4];" \
        : "=r"(r0), "=r"(r1), "=r"(r2), "=r"(r3) : "r"(addr))

#define CVT_TF32(r) asm("cvt.rna.tf32.f32 %0, %0;" : "+r"(r))

#define MMA_TF32(c, a, b0, b1) \
    asm volatile("mma.sync.aligned.m16n8k8.row.col.f32.tf32.tf32.f32 " \
        "{%0,%1,%2,%3}, {%4,%5,%6,%7}, {%8,%9}, {%0,%1,%2,%3};" \
        : "+f"((c)[0]), "+f"((c)[1]), "+f"((c)[2]), "+f"((c)[3]) \
        : "r"((a)[0]), "r"((a)[1]), "r"((a)[2]), "r"((a)[3]), "r"(b0), "r"(b1))

// ---------------- kernel 1: Y^T[s][n][k] = sum_i X[k,i] * V_s[i,n] ----------------
__global__ void y_kernel(const float* __restrict__ X,
                         const float* __restrict__ Kmat,
                         const float* __restrict__ comp,
                         float* __restrict__ YT)
{
    __shared__ float Vs[IN_DIM][OUT_DIM + 1];
    __shared__ float Xs[64][IN_DIM + 1];
    const int s  = blockIdx.y;
    const int j0 = blockIdx.x * 64;
    const float c0 = comp[s * 2 + 0];
    const float c1 = comp[s * 2 + 1];

    for (int idx = threadIdx.x; idx < IN_DIM * OUT_DIM; idx += blockDim.x) {
        int i = idx >> 6, o = idx & 63;
        Vs[i][o] = c0 * Kmat[i * OUT_DIM + o] + c1 * Kmat[(IN_DIM + i) * OUT_DIM + o];
    }
    for (int idx = threadIdx.x; idx < 64 * IN_DIM; idx += blockDim.x) {
        int j = idx >> 6, i = idx & 63;
        Xs[j][i] = X[(size_t)(j0 + j) * IN_DIM + i];
    }
    __syncthreads();

    const int jq = (threadIdx.x & 15) * 4;
    const int oq = (threadIdx.x >> 4) * 4;
    float acc[4][4] = {};
    #pragma unroll 8
    for (int i = 0; i < IN_DIM; i++) {
        float xv[4], vv[4];
        #pragma unroll
        for (int a = 0; a < 4; a++) xv[a] = Xs[jq + a][i];
        #pragma unroll
        for (int b = 0; b < 4; b++) vv[b] = Vs[i][oq + b];
        #pragma unroll
        for (int a = 0; a < 4; a++)
            #pragma unroll
            for (int b = 0; b < 4; b++)
                acc[a][b] = fmaf(xv[a], vv[b], acc[a][b]);
    }

    uint32_t* yt_u = reinterpret_cast<uint32_t*>(YT);
    #pragma unroll
    for (int b = 0; b < 4; b++) {
        #pragma unroll
        for (int a = 0; a < 4; a++) {
            uint32_t t;
            asm("cvt.rna.tf32.f32 %0, %1;" : "=r"(t) : "f"(acc[a][b]));   // pre-round to tf32
            yt_u[((size_t)s * OUT_DIM + oq + b) * N_NODES + j0 + jq + a] = t;
        }
    }
}

// ---------------- kernel 2: raw mma.sync tf32 GEMM, split-K (1 relation / CTA) ----------------
__global__ void __launch_bounds__(256, 2)
rgcn_gemm_kernel(const float* __restrict__ A,
                 const float* __restrict__ YT,
                 float* __restrict__ part)
{
    extern __shared__ float sm[];
    const uint32_t sm_base = smem_u32(sm);

    const int tid  = threadIdx.x;
    const int wid  = tid >> 5;
    const int lane = tid & 31;
    const int m0   = blockIdx.x * BM;
    const int s    = blockIdx.y;                // relation == split-K index

    // warp grid: 4 (M) x 2 (N); each warp 32x32
    const int mbase = (wid & 3) * 32;
    const int nbase = (wid >> 2) * 32;

    // ldmatrix per-thread addressing: tile = lane/8, row-in-tile = lane%8
    const int lrow  = lane & 7;
    const int ltile = lane >> 3;

    // A frag (m16 x k8) x4-tile offsets, relative to stage A base (bytes):
    //   tiles: [rows 0-7,k0-3],[rows 8-15,k0-3],[rows 0-7,k4-7],[rows 8-15,k4-7]
    uint32_t aoff[2];
    #pragma unroll
    for (int i = 0; i < 2; i++)
        aoff[i] = (uint32_t)((mbase + 16 * i + lrow + 8 * (ltile & 1)) * PITCHB
                             + 16 * (ltile >> 1));
    // B frag (n16 x k8) x4-tile offsets, relative to stage B base:
    //   tiles: [n0-7,k0-3],[n0-7,k4-7],[n8-15,k0-3],[n8-15,k4-7]
    uint32_t boff[2];
    #pragma unroll
    for (int p = 0; p < 2; p++)
        boff[p] = (uint32_t)((nbase + 16 * p + lrow + 8 * (ltile >> 1)) * PITCHB
                             + 16 * (ltile & 1));

    float c[2][4][4];
    #pragma unroll
    for (int i = 0; i < 2; i++)
        #pragma unroll
        for (int j = 0; j < 4; j++)
            #pragma unroll
            for (int r = 0; r < 4; r++) c[i][j][r] = 0.0f;

    const float* Abase = A  + ((size_t)s * N_NODES + m0) * N_NODES;
    const float* Bbase = YT + ((size_t)s * OUT_DIM) * N_NODES;

    auto issue = [&](int it) {
        const int st = it & (STAGES - 1);
        const int k0 = it << 5;
        const uint32_t a_s = sm_base + (uint32_t)(st * STAGE_BYTES);
        const uint32_t b_s = a_s + (uint32_t)(A_STAGE_FLOATS * 4);
        const float* Ab = Abase + k0;
        const float* Bb = Bbase + k0;
        #pragma unroll
        for (int i = 0; i < 4; i++) {           // 1024 float4 of A
            int v   = tid + i * 256;
            int row = v >> 3;
            int cc  = (v & 7) * 4;
            CP_ASYNC16(a_s + (uint32_t)(row * PITCHB + cc * 4), Ab + (size_t)row * N_NODES + cc);
        }
        #pragma unroll
        for (int i = 0; i < 2; i++) {           // 512 float4 of B
            int v   = tid + i * 256;
            int row = v >> 3;
            int cc  = (v & 7) * 4;
            CP_ASYNC16(b_s + (uint32_t)(row * PITCHB + cc * 4), Bb + (size_t)row * N_NODES + cc);
        }
    };

    #pragma unroll
    for (int p = 0; p < STAGES - 1; p++) { issue(p); CP_COMMIT(); }

    uint32_t af[2][2][4];   // [buf][mtile][reg]
    uint32_t bf[2][2][4];   // [buf][npair][reg]

    for (int it = 0; it < K_ITERS; ++it) {
        CP_WAIT(STAGES - 2);
        __syncthreads();

        const int nx = it + STAGES - 1;
        if (nx < K_ITERS) issue(nx);
        CP_COMMIT();

        const uint32_t sa = sm_base + (uint32_t)((it & (STAGES - 1)) * STAGE_BYTES);
        const uint32_t sb = sa + (uint32_t)(A_STAGE_FLOATS * 4);

        // preload kk=0 fragments
        LDSM_X4(af[0][0][0], af[0][0][1], af[0][0][2], af[0][0][3], sa + aoff[0]);
        LDSM_X4(af[0][1][0], af[0][1][1], af[0][1][2], af[0][1][3], sa + aoff[1]);
        LDSM_X4(bf[0][0][0], bf[0][0][1], bf[0][0][2], bf[0][0][3], sb + boff[0]);
        LDSM_X4(bf[0][1][0], bf[0][1][1], bf[0][1][2], bf[0][1][3], sb + boff[1]);

        #pragma unroll
        for (int kk = 0; kk < 4; kk++) {
            const int cur = kk & 1, nxt = cur ^ 1;
            if (kk < 3) {
                const uint32_t ko = (uint32_t)((kk + 1) * 32);
                LDSM_X4(af[nxt][0][0], af[nxt][0][1], af[nxt][0][2], af[nxt][0][3], sa + aoff[0] + ko);
                LDSM_X4(af[nxt][1][0], af[nxt][1][1], af[nxt][1][2], af[nxt][1][3], sa + aoff[1] + ko);
                LDSM_X4(bf[nxt][0][0], bf[nxt][0][1], bf[nxt][0][2], bf[nxt][0][3], sb + boff[0] + ko);
                LDSM_X4(bf[nxt][1][0], bf[nxt][1][1], bf[nxt][1][2], bf[nxt][1][3], sb + boff[1] + ko);
            }
            // round A to tf32 (B pre-rounded in g_YT)
            #pragma unroll
            for (int i = 0; i < 2; i++)
                #pragma unroll
                for (int r = 0; r < 4; r++) CVT_TF32(af[cur][i][r]);

            #pragma unroll
            for (int i = 0; i < 2; i++) {
                #pragma unroll
                for (int jn = 0; jn < 4; jn++) {
                    const int p = jn >> 1, q = jn & 1;
                    MMA_TF32(c[i][jn], af[cur][i], bf[cur][p][2 * q], bf[cur][p][2 * q + 1]);
                }
            }
        }
    }

    // ---- write partial tile to global (float2 per fragment half) ----
    float* pbase = part + (size_t)s * N_NODES * OUT_DIM + (size_t)m0 * OUT_DIM;
    const int g = lane >> 2, q2 = (lane & 3) * 2;
    #pragma unroll
    for (int i = 0; i < 2; i++) {
        #pragma unroll
        for (int jn = 0; jn < 4; jn++) {
            const int row = mbase + 16 * i + g;
            const int col = nbase + 8 * jn + q2;
            float2 v0 = make_float2(c[i][jn][0], c[i][jn][1]);
            float2 v1 = make_float2(c[i][jn][2], c[i][jn][3]);
            *reinterpret_cast<float2*>(pbase + (size_t)row * OUT_DIM + col)       = v0;
            *reinterpret_cast<float2*>(pbase + (size_t)(row + 8) * OUT_DIM + col) = v1;
        }
    }
}

// ---------------- kernel 3: reduce + bias + relu ----------------
__global__ void reduce_kernel(const float* __restrict__ part,
                              const float* __restrict__ bias,
                              float* __restrict__ out)
{
    const int v = blockIdx.x * blockDim.x + threadIdx.x;   // float4 index
    const int idx = v * 4;
    const int c = idx & (OUT_DIM - 1);
    float4 r;
    float4 p0 = *reinterpret_cast<const float4*>(part + idx);
    float4 p1 = *reinterpret_cast<const float4*>(part + 1ull * N_NODES * OUT_DIM + idx);
    float4 p2 = *reinterpret_cast<const float4*>(part + 2ull * N_NODES * OUT_DIM + idx);
    float4 p3 = *reinterpret_cast<const float4*>(part + 3ull * N_NODES * OUT_DIM + idx);
    r.x = fmaxf((p0.x + p1.x) + (p2.x + p3.x) + __ldg(bias + c + 0), 0.0f);
    r.y = fmaxf((p0.y + p1.y) + (p2.y + p3.y) + __ldg(bias + c + 1), 0.0f);
    r.z = fmaxf((p0.z + p1.z) + (p2.z + p3.z) + __ldg(bias + c + 2), 0.0f);
    r.w = fmaxf((p0.w + p1.w) + (p2.w + p3.w) + __ldg(bias + c + 3), 0.0f);
    *reinterpret_cast<float4*>(out + idx) = r;
}

// ---------------- host launcher ----------------
extern "C" void kernel_launch(void* const* d_in, const int* in_sizes, int n_in,
                              void* d_out, int out_size)
{
    const float* features = (const float*)d_in[0];
    const float* A        = (const float*)d_in[1];
    const float* kern     = (const float*)d_in[2];
    const float* comp     = (const float*)d_in[3];
    const float* bias     = (const float*)d_in[4];
    float* out = (float*)d_out;

    float* yt = nullptr;
    float* part = nullptr;
    cudaGetSymbolAddress((void**)&yt, g_YT);
    cudaGetSymbolAddress((void**)&part, g_part);

    // 1) Y^T = (X @ V_s)^T, tf32-pre-rounded
    y_kernel<<<dim3(N_NODES / 64, SUPPORT), 256>>>(features, kern, comp, yt);

    // 2) split-K GEMM into partials (one relation per CTA, 2 CTAs/SM)
    cudaFuncSetAttribute(rgcn_gemm_kernel,
                         cudaFuncAttributeMaxDynamicSharedMemorySize, GEMM_SMEM);
    rgcn_gemm_kernel<<<dim3(N_NODES / BM, SPLITK), 256, GEMM_SMEM>>>(A, yt, part);

    // 3) reduce partials + bias + relu
    reduce_kernel<<<(N_NODES * OUT_DIM / 4) / 256, 256>>>(part, bias, out);
}